// round 16
// baseline (speedup 1.0000x reference)
#include <cuda_runtime.h>
#include <math.h>
#include <float.h>

#define B 1024
#define P 256
#define F_IN 8
#define H 16
#define K 8

__device__ __forceinline__ float elu_f(float x) {
    return x > 0.0f ? x : expm1f(x);
}

// packed fp32x2 helpers (Blackwell FFMA2)
__device__ __forceinline__ unsigned long long ffma2(unsigned long long a,
                                                    unsigned long long b,
                                                    unsigned long long c) {
    unsigned long long d;
    asm("fma.rn.f32x2 %0, %1, %2, %3;" : "=l"(d) : "l"(a), "l"(b), "l"(c));
    return d;
}
__device__ __forceinline__ unsigned long long addf32x2(unsigned long long a,
                                                       unsigned long long b) {
    unsigned long long d;
    asm("add.rn.f32x2 %0, %1, %2;" : "=l"(d) : "l"(a), "l"(b));
    return d;
}
__device__ __forceinline__ unsigned long long pack2(float lo, float hi) {
    unsigned long long v;
    asm("mov.b64 %0, {%1, %2};" : "=l"(v) : "f"(lo), "f"(hi));
    return v;
}
__device__ __forceinline__ void unpack2(unsigned long long v, float& lo, float& hi) {
    asm("mov.b64 {%0, %1}, %2;" : "=f"(lo), "=f"(hi) : "l"(v));
}

// dot over 16 dims, dual 4-deep chains. s0: packed words 0,2,4,6; s1: 1,3,5,7
// — same shape as the distance-loop dot so dist(i,i) == exactly 0.
__device__ __forceinline__ float dot16_dual(const unsigned long long* a,
                                            const unsigned long long* b) {
    unsigned long long s0 = 0ull, s1 = 0ull;
    s0 = ffma2(a[0], b[0], s0); s1 = ffma2(a[1], b[1], s1);
    s0 = ffma2(a[2], b[2], s0); s1 = ffma2(a[3], b[3], s1);
    s0 = ffma2(a[4], b[4], s0); s1 = ffma2(a[5], b[5], s1);
    s0 = ffma2(a[6], b[6], s0); s1 = ffma2(a[7], b[7], s1);
    unsigned long long s = addf32x2(s0, s1);
    float lo, hi; unpack2(s, lo, hi);
    return lo + hi;
}

// compare-and-swap: a=min, b=max
#define CAS(a, b) do { unsigned int _t = umin(a, b); (b) = umax(a, b); (a) = _t; } while (0)

// merge 8 candidates into sorted-ascending keys[8] (keep lowest 8 of union).
// Candidate sort-8 (Batcher, 19 CAS) is independent of keys.
__device__ __forceinline__ void merge8(unsigned int (&keys)[K],
                                       unsigned int c0, unsigned int c1,
                                       unsigned int c2, unsigned int c3,
                                       unsigned int c4, unsigned int c5,
                                       unsigned int c6, unsigned int c7) {
    CAS(c0, c1); CAS(c2, c3); CAS(c4, c5); CAS(c6, c7);
    CAS(c0, c2); CAS(c1, c3); CAS(c4, c6); CAS(c5, c7);
    CAS(c1, c2); CAS(c5, c6);
    CAS(c0, c4); CAS(c1, c5); CAS(c2, c6); CAS(c3, c7);
    CAS(c2, c4); CAS(c3, c5);
    CAS(c1, c2); CAS(c3, c4); CAS(c5, c6);
    keys[0] = umin(keys[0], c7);
    keys[1] = umin(keys[1], c6);
    keys[2] = umin(keys[2], c5);
    keys[3] = umin(keys[3], c4);
    keys[4] = umin(keys[4], c3);
    keys[5] = umin(keys[5], c2);
    keys[6] = umin(keys[6], c1);
    keys[7] = umin(keys[7], c0);
    CAS(keys[0], keys[4]); CAS(keys[1], keys[5]); CAS(keys[2], keys[6]); CAS(keys[3], keys[7]);
    CAS(keys[0], keys[2]); CAS(keys[1], keys[3]); CAS(keys[4], keys[6]); CAS(keys[5], keys[7]);
    CAS(keys[0], keys[1]); CAS(keys[2], keys[3]); CAS(keys[4], keys[5]); CAS(keys[6], keys[7]);
}

// distance candidates for rows j, j+1 (broadcast smem rows, packed dots)
__device__ __forceinline__ void dist_pair(const float* sh,
                                          const unsigned long long* myh2,
                                          float mysq, float sqa, float sqb, int j,
                                          unsigned int& cA, unsigned int& cB) {
    const ulonglong2* ra = reinterpret_cast<const ulonglong2*>(sh + j * H);
    ulonglong2 a0 = ra[0], a1 = ra[1], a2 = ra[2], a3 = ra[3];
    ulonglong2 d0 = ra[4], d1 = ra[5], d2 = ra[6], d3 = ra[7];
    unsigned long long sA0 = 0ull, sA1 = 0ull, sB0 = 0ull, sB1 = 0ull;
    sA0 = ffma2(myh2[0], a0.x, sA0); sB0 = ffma2(myh2[0], d0.x, sB0);
    sA1 = ffma2(myh2[1], a0.y, sA1); sB1 = ffma2(myh2[1], d0.y, sB1);
    sA0 = ffma2(myh2[2], a1.x, sA0); sB0 = ffma2(myh2[2], d1.x, sB0);
    sA1 = ffma2(myh2[3], a1.y, sA1); sB1 = ffma2(myh2[3], d1.y, sB1);
    sA0 = ffma2(myh2[4], a2.x, sA0); sB0 = ffma2(myh2[4], d2.x, sB0);
    sA1 = ffma2(myh2[5], a2.y, sA1); sB1 = ffma2(myh2[5], d2.y, sB1);
    sA0 = ffma2(myh2[6], a3.x, sA0); sB0 = ffma2(myh2[6], d3.x, sB0);
    sA1 = ffma2(myh2[7], a3.y, sA1); sB1 = ffma2(myh2[7], d3.y, sB1);
    unsigned long long sA = addf32x2(sA0, sA1);
    unsigned long long sB = addf32x2(sB0, sB1);
    float loA, hiA, loB, hiB;
    unpack2(sA, loA, hiA); unpack2(sB, loB, hiB);
    float distA = fmaf(-2.0f, loA + hiA, mysq + sqa);
    float distB = fmaf(-2.0f, loB + hiB, mysq + sqb);
    unsigned int uA = __float_as_uint(fmaxf(distA, 0.0f));
    unsigned int uB = __float_as_uint(fmaxf(distB, 0.0f));
    cA = (uA & 0xFFFFFF00u) | (unsigned)j;
    cB = (uB & 0xFFFFFF00u) | (unsigned)(j + 1);
}

// ---------------- Fused kernel: encode + kNN + EdgeConv + pool + head ----------------
__global__ __launch_bounds__(256, 3) void fused_kernel(
    const float* __restrict__ x,    // [B, P*F_IN]
    const float* __restrict__ W1,   // [16,8]
    const float* __restrict__ W2,   // [16,16]
    const float* __restrict__ b2,   // [16]
    const float* __restrict__ W3,   // [16,16]
    const float* __restrict__ b3,   // [16]
    const float* __restrict__ We,   // [16,32] row o = [Wa_o | Wb_o]
    const float* __restrict__ be,   // [16]
    const float* __restrict__ Wo1,  // [8,16]
    const float* __restrict__ bo1,  // [8]
    const float* __restrict__ Wo2,  // [1,8]
    const float* __restrict__ bo2,  // [1]
    float* __restrict__ out)        // [B,1]
{
    __shared__ __align__(16) float sh[P * H];    // h tile
    __shared__ __align__(16) float sz[P * H];    // z[j] = Wb @ h_j
    __shared__ __align__(16) float ssq[P];
    __shared__ __align__(16) float sW1[H * F_IN];
    __shared__ __align__(16) float sW2[H * H];
    __shared__ __align__(16) float sW3[H * H];
    __shared__ __align__(16) float sWb[H * H];   // Wb
    __shared__ __align__(16) float sWd[H * H];   // Wa - Wb
    __shared__ float sb2[H], sb3[H], sbe[H];
    __shared__ float sred[8 * H];
    __shared__ float sp[H];

    int tid = threadIdx.x;
    int b   = blockIdx.x;

    // ---- phase 0: cooperative weight staging ----
    if (tid < H * F_IN) sW1[tid] = W1[tid];
    if (tid < H * H)   { sW2[tid] = W2[tid]; sW3[tid] = W3[tid]; }
    if (tid < H)       { sb2[tid] = b2[tid]; sb3[tid] = b3[tid]; sbe[tid] = be[tid]; }
    {
        int o = tid >> 4, d = tid & 15;          // 256 threads = 16x16
        float wa = We[o * 2 * H + d];
        float wb = We[o * 2 * H + H + d];
        sWb[o * H + d] = wb;
        sWd[o * H + d] = wa - wb;
    }
    __syncthreads();

    // ---- phase 1: encode my particle ----
    unsigned long long myh2[8];
    float mysq;
    {
        const float4* xin = reinterpret_cast<const float4*>(
            x + ((size_t)b * P + tid) * F_IN);
        float4 a0 = xin[0], a1 = xin[1];
        float in[F_IN] = {a0.x, a0.y, a0.z, a0.w, a1.x, a1.y, a1.z, a1.w};

        float h1[H];
#pragma unroll
        for (int o = 0; o < H; o++) {
            float acc = 0.0f;
#pragma unroll
            for (int d = 0; d < F_IN; d++) acc = fmaf(sW1[o * F_IN + d], in[d], acc);
            h1[o] = elu_f(acc);
        }
        float h2[H];
#pragma unroll
        for (int o = 0; o < H; o++) {
            float acc = sb2[o];
#pragma unroll
            for (int d = 0; d < H; d++) acc = fmaf(sW2[o * H + d], h1[d], acc);
            h2[o] = elu_f(acc);
        }
        float h3[H];
#pragma unroll
        for (int o = 0; o < H; o++) {
            float acc = sb3[o];
#pragma unroll
            for (int d = 0; d < H; d++) acc = fmaf(sW3[o * H + d], h2[d], acc);
            h3[o] = elu_f(acc);
        }
#pragma unroll
        for (int p = 0; p < 8; p++) myh2[p] = pack2(h3[2 * p], h3[2 * p + 1]);

        // squared norm via the SAME dual-chain dot as the distance loop,
        // so dist(i,i) computes to exactly 0.
        mysq = dot16_dual(myh2, myh2);

        // publish h and sq
        float4* dst = reinterpret_cast<float4*>(sh + tid * H);
#pragma unroll
        for (int q = 0; q < 4; q++)
            dst[q] = make_float4(h3[q * 4 + 0], h3[q * 4 + 1], h3[q * 4 + 2], h3[q * 4 + 3]);
        ssq[tid] = mysq;
    }

    // ---- phase 2: publish z = Wb @ h (own particle) ----
    {
        float zv[H];
#pragma unroll
        for (int o = 0; o < H; o++)
            zv[o] = dot16_dual(myh2,
                reinterpret_cast<const unsigned long long*>(sWb + o * H));
        float4* zdst = reinterpret_cast<float4*>(sz + tid * H);
#pragma unroll
        for (int q = 0; q < 4; q++)
            zdst[q] = make_float4(zv[q * 4 + 0], zv[q * 4 + 1], zv[q * 4 + 2], zv[q * 4 + 3]);
    }
    __syncthreads();

    // ---- phase 3: top-K, 16 rows per iteration (two independent 8-cand blocks) ----
    unsigned int keys[K];   // invariant: sorted ascending
#pragma unroll
    for (int k = 0; k < K; k++) keys[k] = 0xFFFFFFFFu;

    const float4* sq4 = reinterpret_cast<const float4*>(ssq);

#pragma unroll 1
    for (int j = 0; j < P; j += 16) {
        float4 s4a = sq4[(j >> 2) + 0];
        float4 s4b = sq4[(j >> 2) + 1];
        float4 s4c = sq4[(j >> 2) + 2];
        float4 s4d = sq4[(j >> 2) + 3];
        unsigned int c0, c1, c2, c3, c4, c5, c6, c7;
        unsigned int e0, e1, e2, e3, e4, e5, e6, e7;
        dist_pair(sh, myh2, mysq, s4a.x, s4a.y, j + 0,  c0, c1);
        dist_pair(sh, myh2, mysq, s4a.z, s4a.w, j + 2,  c2, c3);
        dist_pair(sh, myh2, mysq, s4b.x, s4b.y, j + 4,  c4, c5);
        dist_pair(sh, myh2, mysq, s4b.z, s4b.w, j + 6,  c6, c7);
        dist_pair(sh, myh2, mysq, s4c.x, s4c.y, j + 8,  e0, e1);
        dist_pair(sh, myh2, mysq, s4c.z, s4c.w, j + 10, e2, e3);
        dist_pair(sh, myh2, mysq, s4d.x, s4d.y, j + 12, e4, e5);
        dist_pair(sh, myh2, mysq, s4d.z, s4d.w, j + 14, e6, e7);
        merge8(keys, c0, c1, c2, c3, c4, c5, c6, c7);
        merge8(keys, e0, e1, e2, e3, e4, e5, e6, e7);
    }

    // ---- phase 4: EdgeConv  node = elu(be + (Wa-Wb).xi + max_k z[jk]) ----
    float best[H];
#pragma unroll
    for (int o = 0; o < H; o++) best[o] = -FLT_MAX;
#pragma unroll
    for (int k = 0; k < K; k++) {
        int j = (int)(keys[k] & 0xFFu);
        const float4* zr = reinterpret_cast<const float4*>(sz + j * H);
        float4 z0 = zr[0], z1 = zr[1], z2 = zr[2], z3 = zr[3];
        best[0]  = fmaxf(best[0],  z0.x); best[1]  = fmaxf(best[1],  z0.y);
        best[2]  = fmaxf(best[2],  z0.z); best[3]  = fmaxf(best[3],  z0.w);
        best[4]  = fmaxf(best[4],  z1.x); best[5]  = fmaxf(best[5],  z1.y);
        best[6]  = fmaxf(best[6],  z1.z); best[7]  = fmaxf(best[7],  z1.w);
        best[8]  = fmaxf(best[8],  z2.x); best[9]  = fmaxf(best[9],  z2.y);
        best[10] = fmaxf(best[10], z2.z); best[11] = fmaxf(best[11], z2.w);
        best[12] = fmaxf(best[12], z3.x); best[13] = fmaxf(best[13], z3.y);
        best[14] = fmaxf(best[14], z3.z); best[15] = fmaxf(best[15], z3.w);
    }

    float node[H];
#pragma unroll
    for (int o = 0; o < H; o++) {
        float d = dot16_dual(myh2,
            reinterpret_cast<const unsigned long long*>(sWd + o * H));
        node[o] = elu_f(sbe[o] + d + best[o]);
    }

    // ---- phase 5: mean pool over 256 nodes ----
#pragma unroll
    for (int o = 0; o < H; o++) {
        float v = node[o];
#pragma unroll
        for (int off = 16; off >= 1; off >>= 1)
            v += __shfl_xor_sync(0xffffffffu, v, off);
        if ((tid & 31) == 0) sred[(tid >> 5) * H + o] = v;
    }
    __syncthreads();
    if (tid < H) {
        float s = 0.0f;
#pragma unroll
        for (int w = 0; w < 8; w++) s += sred[w * H + tid];
        sp[tid] = s * (1.0f / 256.0f);
    }
    __syncthreads();

    // ---- phase 6: head MLP + sigmoid (first warp) ----
    if (tid < 32) {
        float hv = 0.0f;
        if (tid < 8) {
            float acc = bo1[tid];
#pragma unroll
            for (int d = 0; d < H; d++) acc = fmaf(Wo1[tid * H + d], sp[d], acc);
            hv = elu_f(acc) * Wo2[tid];
        }
#pragma unroll
        for (int off = 4; off >= 1; off >>= 1)
            hv += __shfl_xor_sync(0xffffffffu, hv, off);
        if (tid == 0) out[b] = 1.0f / (1.0f + expf(-(hv + bo2[0])));
    }
}

extern "C" void kernel_launch(void* const* d_in, const int* in_sizes, int n_in,
                              void* d_out, int out_size) {
    const float* x   = (const float*)d_in[0];
    const float* W1  = (const float*)d_in[1];
    const float* W2  = (const float*)d_in[2];
    const float* b2  = (const float*)d_in[3];
    const float* W3  = (const float*)d_in[4];
    const float* b3  = (const float*)d_in[5];
    const float* We  = (const float*)d_in[6];
    const float* be  = (const float*)d_in[7];
    const float* Wo1 = (const float*)d_in[8];
    const float* bo1 = (const float*)d_in[9];
    const float* Wo2 = (const float*)d_in[10];
    const float* bo2 = (const float*)d_in[11];

    fused_kernel<<<B, 256>>>(x, W1, W2, b2, W3, b3, We, be,
                             Wo1, bo1, Wo2, bo2, (float*)d_out);
}

// round 17
// speedup vs baseline: 1.0277x; 1.0277x over previous
#include <cuda_runtime.h>
#include <math.h>
#include <float.h>

#define B 1024
#define P 256
#define F_IN 8
#define H 16
#define K 8

__device__ __forceinline__ float elu_f(float x) {
    return x > 0.0f ? x : expm1f(x);
}

// packed fp32x2 helpers (Blackwell FFMA2)
__device__ __forceinline__ unsigned long long ffma2(unsigned long long a,
                                                    unsigned long long b,
                                                    unsigned long long c) {
    unsigned long long d;
    asm("fma.rn.f32x2 %0, %1, %2, %3;" : "=l"(d) : "l"(a), "l"(b), "l"(c));
    return d;
}
__device__ __forceinline__ unsigned long long addf32x2(unsigned long long a,
                                                       unsigned long long b) {
    unsigned long long d;
    asm("add.rn.f32x2 %0, %1, %2;" : "=l"(d) : "l"(a), "l"(b));
    return d;
}
__device__ __forceinline__ unsigned long long pack2(float lo, float hi) {
    unsigned long long v;
    asm("mov.b64 %0, {%1, %2};" : "=l"(v) : "f"(lo), "f"(hi));
    return v;
}
__device__ __forceinline__ void unpack2(unsigned long long v, float& lo, float& hi) {
    asm("mov.b64 {%0, %1}, %2;" : "=f"(lo), "=f"(hi) : "l"(v));
}

// dot over 16 dims, dual 4-deep chains. s0: packed words 0,2,4,6; s1: 1,3,5,7
// — same shape as the distance-loop dot so dist(i,i) == exactly 0.
__device__ __forceinline__ float dot16_dual(const unsigned long long* a,
                                            const unsigned long long* b) {
    unsigned long long s0 = 0ull, s1 = 0ull;
    s0 = ffma2(a[0], b[0], s0); s1 = ffma2(a[1], b[1], s1);
    s0 = ffma2(a[2], b[2], s0); s1 = ffma2(a[3], b[3], s1);
    s0 = ffma2(a[4], b[4], s0); s1 = ffma2(a[5], b[5], s1);
    s0 = ffma2(a[6], b[6], s0); s1 = ffma2(a[7], b[7], s1);
    unsigned long long s = addf32x2(s0, s1);
    float lo, hi; unpack2(s, lo, hi);
    return lo + hi;
}

// compare-and-swap: a=min, b=max
#define CAS(a, b) do { unsigned int _t = umin(a, b); (b) = umax(a, b); (a) = _t; } while (0)

// merge 4 candidates into sorted-ascending keys[8] (keep lowest 8 of union)
__device__ __forceinline__ void merge4(unsigned int (&keys)[K],
                                       unsigned int c0, unsigned int c1,
                                       unsigned int c2, unsigned int c3) {
    CAS(c0, c1); CAS(c2, c3); CAS(c0, c2); CAS(c1, c3); CAS(c1, c2);
    keys[4] = umin(keys[4], c3);
    keys[5] = umin(keys[5], c2);
    keys[6] = umin(keys[6], c1);
    keys[7] = umin(keys[7], c0);
    CAS(keys[0], keys[4]); CAS(keys[1], keys[5]); CAS(keys[2], keys[6]); CAS(keys[3], keys[7]);
    CAS(keys[0], keys[2]); CAS(keys[1], keys[3]); CAS(keys[4], keys[6]); CAS(keys[5], keys[7]);
    CAS(keys[0], keys[1]); CAS(keys[2], keys[3]); CAS(keys[4], keys[5]); CAS(keys[6], keys[7]);
}

// distance candidates for rows j, j+1 (broadcast smem rows, packed dots)
__device__ __forceinline__ void dist_pair(const float* sh,
                                          const unsigned long long* myh2,
                                          float mysq, float sqa, float sqb, int j,
                                          unsigned int& cA, unsigned int& cB) {
    const ulonglong2* ra = reinterpret_cast<const ulonglong2*>(sh + j * H);
    ulonglong2 a0 = ra[0], a1 = ra[1], a2 = ra[2], a3 = ra[3];
    ulonglong2 d0 = ra[4], d1 = ra[5], d2 = ra[6], d3 = ra[7];
    unsigned long long sA0 = 0ull, sA1 = 0ull, sB0 = 0ull, sB1 = 0ull;
    sA0 = ffma2(myh2[0], a0.x, sA0); sB0 = ffma2(myh2[0], d0.x, sB0);
    sA1 = ffma2(myh2[1], a0.y, sA1); sB1 = ffma2(myh2[1], d0.y, sB1);
    sA0 = ffma2(myh2[2], a1.x, sA0); sB0 = ffma2(myh2[2], d1.x, sB0);
    sA1 = ffma2(myh2[3], a1.y, sA1); sB1 = ffma2(myh2[3], d1.y, sB1);
    sA0 = ffma2(myh2[4], a2.x, sA0); sB0 = ffma2(myh2[4], d2.x, sB0);
    sA1 = ffma2(myh2[5], a2.y, sA1); sB1 = ffma2(myh2[5], d2.y, sB1);
    sA0 = ffma2(myh2[6], a3.x, sA0); sB0 = ffma2(myh2[6], d3.x, sB0);
    sA1 = ffma2(myh2[7], a3.y, sA1); sB1 = ffma2(myh2[7], d3.y, sB1);
    unsigned long long sA = addf32x2(sA0, sA1);
    unsigned long long sB = addf32x2(sB0, sB1);
    float loA, hiA, loB, hiB;
    unpack2(sA, loA, hiA); unpack2(sB, loB, hiB);
    float distA = fmaf(-2.0f, loA + hiA, mysq + sqa);
    float distB = fmaf(-2.0f, loB + hiB, mysq + sqb);
    unsigned int uA = __float_as_uint(fmaxf(distA, 0.0f));
    unsigned int uB = __float_as_uint(fmaxf(distB, 0.0f));
    cA = (uA & 0xFFFFFF00u) | (unsigned)j;
    cB = (uB & 0xFFFFFF00u) | (unsigned)(j + 1);
}

// ---------------- Fused kernel: encode + kNN + EdgeConv + pool + head ----------------
__global__ __launch_bounds__(256, 3) void fused_kernel(
    const float* __restrict__ x,    // [B, P*F_IN]
    const float* __restrict__ W1,   // [16,8]
    const float* __restrict__ W2,   // [16,16]
    const float* __restrict__ b2,   // [16]
    const float* __restrict__ W3,   // [16,16]
    const float* __restrict__ b3,   // [16]
    const float* __restrict__ We,   // [16,32] row o = [Wa_o | Wb_o]
    const float* __restrict__ be,   // [16]
    const float* __restrict__ Wo1,  // [8,16]
    const float* __restrict__ bo1,  // [8]
    const float* __restrict__ Wo2,  // [1,8]
    const float* __restrict__ bo2,  // [1]
    float* __restrict__ out)        // [B,1]
{
    __shared__ __align__(16) float sh[P * H];    // h tile
    __shared__ __align__(16) float sz[P * H];    // z[j] = Wb @ h_j
    __shared__ __align__(16) float ssq[P];
    __shared__ __align__(16) float sW1[H * F_IN];
    __shared__ __align__(16) float sW2[H * H];
    __shared__ __align__(16) float sW3[H * H];
    __shared__ __align__(16) float sWb[H * H];   // Wb
    __shared__ __align__(16) float sWd[H * H];   // Wa - Wb
    __shared__ float sb2[H], sb3[H], sbe[H];
    __shared__ float sred[8 * H];
    __shared__ float sp[H];

    int tid = threadIdx.x;
    int b   = blockIdx.x;

    // ---- phase 0: cooperative weight staging ----
    if (tid < H * F_IN) sW1[tid] = W1[tid];
    if (tid < H * H)   { sW2[tid] = W2[tid]; sW3[tid] = W3[tid]; }
    if (tid < H)       { sb2[tid] = b2[tid]; sb3[tid] = b3[tid]; sbe[tid] = be[tid]; }
    {
        int o = tid >> 4, d = tid & 15;          // 256 threads = 16x16
        float wa = We[o * 2 * H + d];
        float wb = We[o * 2 * H + H + d];
        sWb[o * H + d] = wb;
        sWd[o * H + d] = wa - wb;
    }
    __syncthreads();

    // ---- phase 1: encode my particle ----
    unsigned long long myh2[8];
    float mysq;
    {
        const float4* xin = reinterpret_cast<const float4*>(
            x + ((size_t)b * P + tid) * F_IN);
        float4 a0 = xin[0], a1 = xin[1];
        float in[F_IN] = {a0.x, a0.y, a0.z, a0.w, a1.x, a1.y, a1.z, a1.w};

        float h1[H];
#pragma unroll
        for (int o = 0; o < H; o++) {
            float acc = 0.0f;
#pragma unroll
            for (int d = 0; d < F_IN; d++) acc = fmaf(sW1[o * F_IN + d], in[d], acc);
            h1[o] = elu_f(acc);
        }
        float h2[H];
#pragma unroll
        for (int o = 0; o < H; o++) {
            float acc = sb2[o];
#pragma unroll
            for (int d = 0; d < H; d++) acc = fmaf(sW2[o * H + d], h1[d], acc);
            h2[o] = elu_f(acc);
        }
        float h3[H];
#pragma unroll
        for (int o = 0; o < H; o++) {
            float acc = sb3[o];
#pragma unroll
            for (int d = 0; d < H; d++) acc = fmaf(sW3[o * H + d], h2[d], acc);
            h3[o] = elu_f(acc);
        }
#pragma unroll
        for (int p = 0; p < 8; p++) myh2[p] = pack2(h3[2 * p], h3[2 * p + 1]);

        // squared norm via the SAME dual-chain dot as the distance loop,
        // so dist(i,i) computes to exactly 0.
        mysq = dot16_dual(myh2, myh2);

        // publish h and sq
        float4* dst = reinterpret_cast<float4*>(sh + tid * H);
#pragma unroll
        for (int q = 0; q < 4; q++)
            dst[q] = make_float4(h3[q * 4 + 0], h3[q * 4 + 1], h3[q * 4 + 2], h3[q * 4 + 3]);
        ssq[tid] = mysq;
    }

    // ---- phase 2: publish z = Wb @ h (own particle) ----
    {
        float zv[H];
#pragma unroll
        for (int o = 0; o < H; o++)
            zv[o] = dot16_dual(myh2,
                reinterpret_cast<const unsigned long long*>(sWb + o * H));
        float4* zdst = reinterpret_cast<float4*>(sz + tid * H);
#pragma unroll
        for (int q = 0; q < 4; q++)
            zdst[q] = make_float4(zv[q * 4 + 0], zv[q * 4 + 1], zv[q * 4 + 2], zv[q * 4 + 3]);
    }
    __syncthreads();

    // ---- phase 3: top-K, 8 rows per iteration (two independent 4-cand blocks) ----
    unsigned int keys[K];   // invariant: sorted ascending
#pragma unroll
    for (int k = 0; k < K; k++) keys[k] = 0xFFFFFFFFu;

    const float4* sq4 = reinterpret_cast<const float4*>(ssq);

#pragma unroll 1
    for (int j = 0; j < P; j += 8) {
        float4 s4a = sq4[(j >> 2) + 0];
        float4 s4b = sq4[(j >> 2) + 1];
        unsigned int c0, c1, c2, c3, c4, c5, c6, c7;
        dist_pair(sh, myh2, mysq, s4a.x, s4a.y, j + 0, c0, c1);
        dist_pair(sh, myh2, mysq, s4a.z, s4a.w, j + 2, c2, c3);
        dist_pair(sh, myh2, mysq, s4b.x, s4b.y, j + 4, c4, c5);
        dist_pair(sh, myh2, mysq, s4b.z, s4b.w, j + 6, c6, c7);
        merge4(keys, c0, c1, c2, c3);
        merge4(keys, c4, c5, c6, c7);
    }

    // ---- phase 4: EdgeConv  node = elu(be + (Wa-Wb).xi + max_k z[jk]) ----
    float best[H];
#pragma unroll
    for (int o = 0; o < H; o++) best[o] = -FLT_MAX;
#pragma unroll
    for (int k = 0; k < K; k++) {
        int j = (int)(keys[k] & 0xFFu);
        const float4* zr = reinterpret_cast<const float4*>(sz + j * H);
        float4 z0 = zr[0], z1 = zr[1], z2 = zr[2], z3 = zr[3];
        best[0]  = fmaxf(best[0],  z0.x); best[1]  = fmaxf(best[1],  z0.y);
        best[2]  = fmaxf(best[2],  z0.z); best[3]  = fmaxf(best[3],  z0.w);
        best[4]  = fmaxf(best[4],  z1.x); best[5]  = fmaxf(best[5],  z1.y);
        best[6]  = fmaxf(best[6],  z1.z); best[7]  = fmaxf(best[7],  z1.w);
        best[8]  = fmaxf(best[8],  z2.x); best[9]  = fmaxf(best[9],  z2.y);
        best[10] = fmaxf(best[10], z2.z); best[11] = fmaxf(best[11], z2.w);
        best[12] = fmaxf(best[12], z3.x); best[13] = fmaxf(best[13], z3.y);
        best[14] = fmaxf(best[14], z3.z); best[15] = fmaxf(best[15], z3.w);
    }

    float node[H];
#pragma unroll
    for (int o = 0; o < H; o++) {
        float d = dot16_dual(myh2,
            reinterpret_cast<const unsigned long long*>(sWd + o * H));
        node[o] = elu_f(sbe[o] + d + best[o]);
    }

    // ---- phase 5: mean pool over 256 nodes ----
#pragma unroll
    for (int o = 0; o < H; o++) {
        float v = node[o];
#pragma unroll
        for (int off = 16; off >= 1; off >>= 1)
            v += __shfl_xor_sync(0xffffffffu, v, off);
        if ((tid & 31) == 0) sred[(tid >> 5) * H + o] = v;
    }
    __syncthreads();
    if (tid < H) {
        float s = 0.0f;
#pragma unroll
        for (int w = 0; w < 8; w++) s += sred[w * H + tid];
        sp[tid] = s * (1.0f / 256.0f);
    }
    __syncthreads();

    // ---- phase 6: head MLP + sigmoid (first warp) ----
    if (tid < 32) {
        float hv = 0.0f;
        if (tid < 8) {
            float acc = bo1[tid];
#pragma unroll
            for (int d = 0; d < H; d++) acc = fmaf(Wo1[tid * H + d], sp[d], acc);
            hv = elu_f(acc) * Wo2[tid];
        }
#pragma unroll
        for (int off = 4; off >= 1; off >>= 1)
            hv += __shfl_xor_sync(0xffffffffu, hv, off);
        if (tid == 0) out[b] = 1.0f / (1.0f + expf(-(hv + bo2[0])));
    }
}

extern "C" void kernel_launch(void* const* d_in, const int* in_sizes, int n_in,
                              void* d_out, int out_size) {
    const float* x   = (const float*)d_in[0];
    const float* W1  = (const float*)d_in[1];
    const float* W2  = (const float*)d_in[2];
    const float* b2  = (const float*)d_in[3];
    const float* W3  = (const float*)d_in[4];
    const float* b3  = (const float*)d_in[5];
    const float* We  = (const float*)d_in[6];
    const float* be  = (const float*)d_in[7];
    const float* Wo1 = (const float*)d_in[8];
    const float* bo1 = (const float*)d_in[9];
    const float* Wo2 = (const float*)d_in[10];
    const float* bo2 = (const float*)d_in[11];

    fused_kernel<<<B, 256>>>(x, W1, W2, b2, W3, b3, We, be,
                             Wo1, bo1, Wo2, bo2, (float*)d_out);
}